// round 1
// baseline (speedup 1.0000x reference)
#include <cuda_runtime.h>

// ContextAwareTracker: LSTM encoder(50) + decoder(12), B=16384, H=128, I=5.
// Strategy: persistent per-CTA hidden/cell state in SMEM/regs across all 62
// steps; weights pre-packed (transposed, gate-chunked) by a prep kernel;
// FFMA-bound fp32 GEMM with float4 LDS.

#define BDIM 256
#define BB   128          // batch rows per CTA
#define NCTA 128          // 16384 / 128
#define NCH  16           // gate chunks per step (8 hidden units each)
#define CHUNK_FLOATS 4352 // padded chunk block (134*32 = 4288 used)
#define CHUNK_USED   4288
#define CHUNK_F4     1072 // 4288/4

__device__ float g_wpack[2 * NCH * CHUNK_FLOATS];

// Pack weights: per (net, chunk): rows 0..127 = Whh^T slice [k][c],
// rows 128..132 = Wih^T slice [i][c], row 133 = bih+bhh.
// Column c = gate*8 + uu  (gate: 0=i,1=f,2=g,3=o), global gate row
// j = gate*128 + ch*8 + uu.
__global__ void prep_kernel(const float* __restrict__ eWih, const float* __restrict__ eWhh,
                            const float* __restrict__ ebih, const float* __restrict__ ebhh,
                            const float* __restrict__ dWih, const float* __restrict__ dWhh,
                            const float* __restrict__ dbih, const float* __restrict__ dbhh)
{
    int idx = blockIdx.x * blockDim.x + threadIdx.x;
    const int total = 2 * NCH * CHUNK_USED;
    if (idx >= total) return;
    int net = idx / (NCH * CHUNK_USED);
    int rem = idx % (NCH * CHUNK_USED);
    int ch  = rem / CHUNK_USED;
    int pos = rem % CHUNK_USED;
    int kk  = pos >> 5;    // 0..133
    int c   = pos & 31;
    int gate = c >> 3, uu = c & 7;
    int j = gate * 128 + ch * 8 + uu;
    const float* Wih = net ? dWih : eWih;
    const float* Whh = net ? dWhh : eWhh;
    const float* bih = net ? dbih : ebih;
    const float* bhh = net ? dbhh : ebhh;
    float v;
    if (kk < 128)      v = Whh[j * 128 + kk];
    else if (kk < 133) v = Wih[j * 5 + (kk - 128)];
    else               v = bih[j] + bhh[j];
    g_wpack[(net * NCH + ch) * CHUNK_FLOATS + kk * 32 + c] = v;
}

__device__ __forceinline__ float sigf(float x) {
    return __fdividef(1.f, 1.f + __expf(-x));
}
__device__ __forceinline__ float tanh_(float x) {
    return fmaf(2.f, sigf(2.f * x), -1.f);
}

__global__ __launch_bounds__(BDIM, 1)
void lstm_kernel(const float* __restrict__ x,
                 const float* __restrict__ linW,
                 const float* __restrict__ linb,
                 float* __restrict__ out)
{
    extern __shared__ float sm[];
    float* hbuf0 = sm;                    // [128][128]  h (k-major: hT[k][r])
    float* hbuf1 = hbuf0 + 128 * 128;     // [128][128]  ping-pong
    float* wall  = hbuf1 + 128 * 128;     // [134+pad][32] staged weight chunk
    float* gsh   = wall + CHUNK_FLOATS;   // [32][132]   gates chunk (padded rows)
    float* xT    = gsh + 32 * 132;        // [5][128]    current inputs (k-major)

    const int tid = threadIdx.x;
    const int rb  = blockIdx.x * BB;

    const int tr = tid >> 3;   // 0..31 -> rows tr*4..+3
    const int tc = tid & 7;    // 0..7  -> cols tc*4..+3
    const int r0 = tr * 4;
    const int c0 = tc * 4;

    // zero initial h
    for (int i = tid; i < 128 * 128; i += BDIM) hbuf0[i] = 0.f;

    // cell state: fixed per-thread ownership, 4 per chunk x 16 chunks
    float c_loc[64];
    #pragma unroll
    for (int i = 0; i < 64; i++) c_loc[i] = 0.f;

    // initial weight prefetch (enc, chunk 0)
    float4 pf[5];
    {
        const float4* src = (const float4*)g_wpack;
        #pragma unroll
        for (int j = 0; j < 5; j++) {
            int i4 = tid + j * BDIM;
            if (i4 < CHUNK_F4) pf[j] = src[i4];
        }
    }
    __syncthreads();

    float* hc = hbuf0;   // current h (read by GEMM)
    float* hn = hbuf1;   // next h (written by elementwise)

    for (int t = 0; t < 62; t++) {
        const int net = (t < 50) ? 0 : 1;

        // stage encoder inputs x[:, t, :] (decoder inputs live in xT already:
        // t=50 reuses x[:,49,:] staged at t=49; preds overwrite xT[0..1]).
        if (t < 50 && tid < 128) {
            const float* xp = x + (size_t)(rb + tid) * 250 + t * 5;
            #pragma unroll
            for (int i = 0; i < 5; i++) xT[i * 128 + tid] = xp[i];
        }

        for (int ch = 0; ch < NCH; ch++) {
            // commit prefetched chunk to smem
            {
                float4* dst = (float4*)wall;
                #pragma unroll
                for (int j = 0; j < 5; j++) {
                    int i4 = tid + j * BDIM;
                    if (i4 < CHUNK_F4) dst[i4] = pf[j];
                }
            }
            __syncthreads();

            // prefetch next chunk into registers (overlaps with GEMM below)
            {
                int nnet = (ch < NCH - 1) ? net : (((t + 1) < 50) ? 0 : 1);
                int nch  = (ch < NCH - 1) ? ch + 1 : 0;
                const float4* src =
                    (const float4*)(g_wpack + (size_t)(nnet * NCH + nch) * CHUNK_FLOATS);
                #pragma unroll
                for (int j = 0; j < 5; j++) {
                    int i4 = tid + j * BDIM;
                    if (i4 < CHUNK_F4) pf[j] = src[i4];
                }
            }

            // ---- GEMM: 128 rows x 32 gate-cols over k=128 (h) + 5 (x) ----
            float a[4][4];
            {
                float4 bv = *(const float4*)(wall + 133 * 32 + c0);
                float bc[4] = {bv.x, bv.y, bv.z, bv.w};
                #pragma unroll
                for (int ri = 0; ri < 4; ri++)
                    #pragma unroll
                    for (int ci = 0; ci < 4; ci++) a[ri][ci] = bc[ci];
            }
            const float* hp = hc + r0;
            const float* wp = wall + c0;
            #pragma unroll 8
            for (int k = 0; k < 128; k++) {
                float4 hv = *(const float4*)(hp + k * 128);
                float4 wv = *(const float4*)(wp + k * 32);
                float hr[4] = {hv.x, hv.y, hv.z, hv.w};
                float wc[4] = {wv.x, wv.y, wv.z, wv.w};
                #pragma unroll
                for (int ri = 0; ri < 4; ri++)
                    #pragma unroll
                    for (int ci = 0; ci < 4; ci++)
                        a[ri][ci] = fmaf(hr[ri], wc[ci], a[ri][ci]);
            }
            #pragma unroll
            for (int i = 0; i < 5; i++) {
                float4 hv = *(const float4*)(xT + i * 128 + r0);
                float4 wv = *(const float4*)(wall + (128 + i) * 32 + c0);
                float hr[4] = {hv.x, hv.y, hv.z, hv.w};
                float wc[4] = {wv.x, wv.y, wv.z, wv.w};
                #pragma unroll
                for (int ri = 0; ri < 4; ri++)
                    #pragma unroll
                    for (int ci = 0; ci < 4; ci++)
                        a[ri][ci] = fmaf(hr[ri], wc[ci], a[ri][ci]);
            }
            // gates -> smem  (gsh[c][r], padded row stride 132)
            #pragma unroll
            for (int ci = 0; ci < 4; ci++) {
                *(float4*)(gsh + (c0 + ci) * 132 + r0) =
                    make_float4(a[0][ci], a[1][ci], a[2][ci], a[3][ci]);
            }
            __syncthreads();

            // ---- elementwise: 128 rows x 8 units, all 256 threads ----
            #pragma unroll
            for (int it = 0; it < 4; it++) {
                int idx = it * BDIM + tid;
                int r   = idx & 127;
                int uu  = idx >> 7;          // 0..7
                float iv = sigf (gsh[(     uu) * 132 + r]);
                float fv = sigf (gsh[( 8 + uu) * 132 + r]);
                float gv = tanh_(gsh[(16 + uu) * 132 + r]);
                float ov = sigf (gsh[(24 + uu) * 132 + r]);
                float cn = fmaf(fv, c_loc[ch * 4 + it], iv * gv);
                c_loc[ch * 4 + it] = cn;
                hn[(ch * 8 + uu) * 128 + r] = ov * tanh_(cn);
            }
        }
        __syncthreads();   // all of hn visible

        if (net == 1) {
            // pred = h_new @ lin_W^T + lin_b ; write out and feed back into xT
            int dt = t - 50;
            int r  = tid & 127;
            int j  = tid >> 7;               // 0..1
            float acc = linb[j];
            const float* lw = linW + j * 128;
            #pragma unroll 8
            for (int u = 0; u < 128; u++)
                acc = fmaf(hn[u * 128 + r], lw[u], acc);
            out[((size_t)(rb + r) * 12 + dt) * 2 + j] = acc;
            xT[j * 128 + r] = acc;           // next dec_in (static stays in xT[2..4])
        }

        // swap h buffers
        float* tmp = hc; hc = hn; hn = tmp;
    }
}

extern "C" void kernel_launch(void* const* d_in, const int* in_sizes, int n_in,
                              void* d_out, int out_size)
{
    const float* x    = (const float*)d_in[0];
    const float* eWih = (const float*)d_in[1];
    const float* eWhh = (const float*)d_in[2];
    const float* ebih = (const float*)d_in[3];
    const float* ebhh = (const float*)d_in[4];
    const float* dWih = (const float*)d_in[5];
    const float* dWhh = (const float*)d_in[6];
    const float* dbih = (const float*)d_in[7];
    const float* dbhh = (const float*)d_in[8];
    const float* lW   = (const float*)d_in[9];
    const float* lb   = (const float*)d_in[10];
    float* out = (float*)d_out;

    const int smem_bytes = (2 * 128 * 128 + CHUNK_FLOATS + 32 * 132 + 5 * 128) * 4;
    cudaFuncSetAttribute(lstm_kernel, cudaFuncAttributeMaxDynamicSharedMemorySize, smem_bytes);

    const int prep_total = 2 * NCH * CHUNK_USED;
    prep_kernel<<<(prep_total + 255) / 256, 256>>>(eWih, eWhh, ebih, ebhh,
                                                   dWih, dWhh, dbih, dbhh);
    lstm_kernel<<<NCTA, BDIM, smem_bytes>>>(x, lW, lb, out);
}